// round 15
// baseline (speedup 1.0000x reference)
#include <cuda_runtime.h>
#include <cuda_fp16.h>
#include <math.h>
#include <stdint.h>

#define S_ 2048
#define V_ 100
#define B_ 64
#define H_ 256
#define N_ 4
#define D_ 128

__device__ __align__(16) __half g_WhhT_h[256 * 1536];
__device__ __align__(16) __half g_WopT_h[256 * 512];
__device__ __align__(16) __half g_WqT_h [16384], g_WkT_h [16384], g_WvT_h [16384];
__device__ __align__(16) __half g_Wf1T_h[16384], g_Wf2T_h[16384], g_WwoT_h[16384];
__device__ __align__(16) __half g_Wr2_h [4 * 100 * 128];   // [(nn*100+v)*128 + k]
__device__ __align__(16) float g_tab [100 * 3072];
__device__ __align__(16) float g_McT [128 * 3072];
__device__ int g_fb_active;

// smem layout (bytes)
#define SM_F       163840                // float region starts after 5 fp16 mats
#define NFLOATS    8604
#define SMEM_BYTES (163840 + NFLOATS * 4)

__device__ __forceinline__ void ffma2(unsigned long long& d, unsigned long long a, unsigned long long b) {
    asm("fma.rn.f32x2 %0, %1, %2, %3;" : "=l"(d) : "l"(a), "l"(b), "l"(d));
}
__device__ __forceinline__ unsigned long long bcast2(float x) {
    unsigned long long r; asm("mov.b64 %0, {%1, %1};" : "=l"(r) : "f"(x)); return r;
}
__device__ __forceinline__ unsigned long long pk2(float2 f) {
    unsigned long long r; asm("mov.b64 %0, {%1, %2};" : "=l"(r) : "f"(f.x), "f"(f.y)); return r;
}
__device__ __forceinline__ float sigf(float x) { return 1.0f / (1.0f + expf(-x)); }
__device__ __forceinline__ float geluf(float x) { return 0.5f * x * (1.0f + erff(x * 0.7071067811865475f)); }

__device__ __forceinline__ uint32_t smem_u32(const void* p) { return (uint32_t)__cvta_generic_to_shared(p); }
__device__ __forceinline__ uint32_t mapa_rank(uint32_t a, uint32_t rk) {
    uint32_t r; asm("mapa.shared::cluster.u32 %0, %1, %2;" : "=r"(r) : "r"(a), "r"(rk)); return r;
}
__device__ __forceinline__ void stc_f32(uint32_t a, float v) {
    asm volatile("st.shared::cluster.f32 [%0], %1;" :: "r"(a), "f"(v) : "memory");
}
#define CLUSTER_SYNC() do { \
    asm volatile("barrier.cluster.arrive.aligned;" ::: "memory"); \
    asm volatile("barrier.cluster.wait.aligned;" ::: "memory"); } while (0)

// ---------------- prep (single kernel; fb-detect by block 0 only -> deterministic) ----------------
__global__ void prep_all(const float* __restrict__ W_ih, const float* __restrict__ b_ih,
                         const float* __restrict__ W_hh_c, const float* __restrict__ W_op,
                         const float* __restrict__ Wq, const float* __restrict__ Wk,
                         const float* __restrict__ Wv, const float* __restrict__ Wf1,
                         const float* __restrict__ Wf2, const float* __restrict__ Wwo,
                         const float* __restrict__ Wr, const float* __restrict__ Wfb,
                         const float* __restrict__ bfb, const float* __restrict__ emb)
{
    int i = blockIdx.x * blockDim.x + threadIdx.x, st = gridDim.x * blockDim.x;
    for (int p = i; p < 256 * 1536; p += st) { int k = p / 1536, o = p - k * 1536; g_WhhT_h[p] = __float2half_rn(W_hh_c[o * 256 + k]); }
    for (int p = i; p < 256 * 512;  p += st) { int k = p >> 9,  o = p & 511;       g_WopT_h[p] = __float2half_rn(W_op[o * 256 + k]); }
    for (int p = i; p < 16384; p += st) {
        int k = p >> 7, d = p & 127;
        g_WqT_h [p] = __float2half_rn(Wq [d * 128 + k]);
        g_WkT_h [p] = __float2half_rn(Wk [d * 128 + k]);
        g_WvT_h [p] = __float2half_rn(Wv [d * 128 + k]);
        g_Wf1T_h[p] = __float2half_rn(Wf1[d * 128 + k]);
        g_Wf2T_h[p] = __float2half_rn(Wf2[d * 128 + k]);
        g_WwoT_h[p] = __float2half_rn(Wwo[d * 128 + k]);
    }
    // Wr: per-output-contiguous layout [(nn*100+v)*128 + k] = Wr[v*512 + nn*128 + k]
    for (int p = i; p < 4 * 100 * 128; p += st) {
        int k = p & 127, row = p >> 7;         // row = nn*100 + v
        int nn = row / 100, v = row - nn * 100;
        g_Wr2_h[p] = __float2half_rn(Wr[v * 512 + nn * 128 + k]);
    }
    for (int p = i; p < 100 * 3072; p += st) {
        int v = p / 3072, o = p - v * 3072;
        const float* wr = W_ih + (size_t)o * 128;
        const float* ev = emb + (size_t)v * 128;
        float acc = b_ih[o];
        #pragma unroll 8
        for (int k = 0; k < 128; ++k) acc = fmaf(wr[k], ev[k] + bfb[k], acc);
        g_tab[p] = acc;
    }
    for (int p = i; p < 128 * 3072; p += st) {
        int kk = p / 3072, o = p - kk * 3072;
        const float* wr = W_ih + (size_t)o * 128;
        const float* fr = Wfb + (size_t)kk * 128;
        float acc = 0.0f;
        #pragma unroll 8
        for (int j = 0; j < 128; ++j) acc = fmaf(wr[j], fr[j], acc);
        g_McT[p] = acc;
    }
    // fb-active detection: block 0 alone scans everything, thread 0 writes (no reset kernel needed)
    if (blockIdx.x == 0) {
        __shared__ int s_nz;
        if (threadIdx.x == 0) s_nz = 0;
        __syncthreads();
        int nz = 0;
        for (int p = threadIdx.x; p < 16384; p += blockDim.x) if (Wfb[p] != 0.0f) nz = 1;
        for (int p = threadIdx.x; p < 128; p += blockDim.x) if (bfb[p] != 0.0f) nz = 1;
        if (nz) atomicOr(&s_nz, 1);
        __syncthreads();
        if (threadIdx.x == 0) g_fb_active = s_nz;
    }
}

// ---- LayerNorm + logits partial for own 2 neurons; 256 threads, named barrier 1 ----
__device__ __forceinline__ void ln_logits_own(
    int u, int r, uint32_t peerlog_paddr,
    const float* __restrict__ gamma, const float* __restrict__ beta,
    const float* sh_rs, float* sh_on, float* sh_red, float* sh_mu, float* sh_rstd,
    float* lnscr, float* ownlog)
{
    int row = u >> 7, d = u & 127, w8 = u >> 5, l = u & 31;
    float v = sh_rs[u];
    float sum = v, sq = v * v;
    #pragma unroll
    for (int off = 16; off; off >>= 1) {
        sum += __shfl_down_sync(0xffffffff, sum, off);
        sq  += __shfl_down_sync(0xffffffff, sq,  off);
    }
    if (l == 0) { sh_red[w8 * 2] = sum; sh_red[w8 * 2 + 1] = sq; }
    asm volatile("bar.sync 1, 256;" ::: "memory");
    if (u < 2) {
        float s = 0.f, q = 0.f;
        #pragma unroll
        for (int j = 0; j < 4; ++j) { s += sh_red[(u * 4 + j) * 2]; q += sh_red[(u * 4 + j) * 2 + 1]; }
        float mu = s * (1.0f / 128.0f);
        sh_mu[u] = mu;
        sh_rstd[u] = rsqrtf(q * (1.0f / 128.0f) - mu * mu + 1e-5f);
    }
    asm volatile("bar.sync 1, 256;" ::: "memory");
    sh_on[u] = (sh_rs[u] - sh_mu[row]) * sh_rstd[row] * gamma[d] + beta[d];
    asm volatile("bar.sync 1, 256;" ::: "memory");
    {
        float a = 0.0f;
        if (d < V_) {
            int nn = r + 2 * row;
            const __half* W = g_Wr2_h + ((size_t)(nn * 100 + d)) * 128;
            const float* on = sh_on + row * 128;
            #pragma unroll
            for (int k4 = 0; k4 < 128; k4 += 8) {
                uint4 w = *(const uint4*)(W + k4);
                float2 f0 = __half22float2(*(const __half2*)&w.x);
                float2 f1 = __half22float2(*(const __half2*)&w.y);
                float2 f2 = __half22float2(*(const __half2*)&w.z);
                float2 f3 = __half22float2(*(const __half2*)&w.w);
                a += f0.x * on[k4]     + f0.y * on[k4 + 1]
                   + f1.x * on[k4 + 2] + f1.y * on[k4 + 3]
                   + f2.x * on[k4 + 4] + f2.y * on[k4 + 5]
                   + f3.x * on[k4 + 6] + f3.y * on[k4 + 7];
            }
        }
        lnscr[u] = a;
    }
    asm volatile("bar.sync 1, 256;" ::: "memory");
    if (u < 128) {
        float tot = lnscr[u] + lnscr[128 + u];
        ownlog[u] = tot;
        stc_f32(peerlog_paddr + u * 4, tot);
    }
}

// ---- fp16 128x128 matvec on own 2 rows from SMEM weights: 256 threads ----
__device__ __forceinline__ void mat128x2sh(int t, const __half* WT,
                                           const float* src, float* scr)
{
    int ks = t >> 5, dg = t & 31;
    const __half* wp = WT + (size_t)(ks * 16) * 128 + dg * 4;
    const float* x0 = src + ks * 16;
    const float* x1 = src + 128 + ks * 16;
    unsigned long long a0 = 0, a1 = 0, b0 = 0, b1 = 0;
    #pragma unroll
    for (int k = 0; k < 16; ++k) {
        uint2 u = *(const uint2*)(wp + (size_t)k * 128);
        unsigned long long w0 = pk2(__half22float2(*(const __half2*)&u.x));
        unsigned long long w1 = pk2(__half22float2(*(const __half2*)&u.y));
        unsigned long long xx0 = bcast2(x0[k]), xx1 = bcast2(x1[k]);
        ffma2(a0, w0, xx0); ffma2(a1, w1, xx0);
        ffma2(b0, w0, xx1); ffma2(b1, w1, xx1);
    }
    ulonglong2 s0; s0.x = a0; s0.y = a1;
    ulonglong2 s1; s1.x = b0; s1.y = b1;
    *(ulonglong2*)(scr + (ks * 2 + 0) * 128 + dg * 4) = s0;
    *(ulonglong2*)(scr + (ks * 2 + 1) * 128 + dg * 4) = s1;
}

__global__ void __launch_bounds__(1024, 1) __cluster_dims__(2, 1, 1)
inn_kernel(const int* __restrict__ x,
           const float* __restrict__ b_hh_c, const float* __restrict__ b_op,
           const float* __restrict__ bq, const float* __restrict__ bk, const float* __restrict__ bv,
           const float* __restrict__ bf1, const float* __restrict__ bf2, const float* __restrict__ bwo,
           const float* __restrict__ gamma, const float* __restrict__ beta,
           const float* __restrict__ br,
           float* __restrict__ out, int write_states)
{
    extern __shared__ __align__(16) char smraw[];
    __half* s_wq  = (__half*)(smraw);
    __half* s_wf1 = s_wq + 3 * 16384;
    __half* s_wf2 = s_wf1 + 16384;
    float* fb_    = (float*)(smraw + SM_F);
    float* sh_h     = fb_;            // 512
    float* scr      = sh_h + 512;     // 3072
    float* lnscr    = scr + 3072;     // 256
    float* kv_all   = lnscr + 256;    // 2048 (2 x 1024)
    float* sh_o     = kv_all + 2048;  // 256
    float* sh_q     = sh_o + 256;     // 256
    float* sh_mx    = sh_q + 256;     // 256
    float* sh_g1    = sh_mx + 256;    // 256
    float* sh_pc    = sh_g1 + 256;    // 256
    float* sh_rs    = sh_pc + 256;    // 256
    float* sh_on    = sh_rs + 256;    // 256
    float* peerlog  = sh_on + 256;    // 256 (2 x 128)
    float* ownlog   = peerlog + 256;  // 128
    float* fbx      = ownlog + 128;   // 256 (2 x 128)
    float* sh_fbown = fbx + 256;      // 128
    float* sh_fb    = sh_fbown + 128; // 128
    float* sh_sc    = sh_fb + 128;    // 8
    float* sh_red   = sh_sc + 8;      // 16
    float* sh_mu    = sh_red + 16;    // 2
    float* sh_rstd  = sh_mu + 2;      // 2

    const int b = blockIdx.x >> 1;
    const int r = blockIdx.x & 1;
    const uint32_t peer = (uint32_t)(r ^ 1);
    const int t = threadIdx.x;

    #pragma unroll
    for (int m = 0; m < 5; ++m) {
        const __half* src = (m == 0) ? g_WqT_h : (m == 1) ? g_WkT_h : (m == 2) ? g_WvT_h
                          : (m == 3) ? g_Wf1T_h : g_Wf2T_h;
        uint4* dst = (uint4*)(s_wq + m * 16384);
        for (int i = t; i < 2048; i += 1024) dst[i] = ((const uint4*)src)[i];
    }
    if (t < 512) sh_h[t] = 0.0f;
    if (t < 128) sh_fb[t] = 0.0f;
    const int fbact = g_fb_active;
    __syncthreads();

    const float inv_sqrt_d = 0.08838834764831845f;

    for (int s = 0; s < S_; ++s) {
        const int p = s & 1;
        float* kvp_loc = kv_all + p * 1024;
        const int tok = __ldg(x + b * S_ + s);

        float gi_r = 0.f, gi_z = 0.f, gi_n = 0.f;
        if (t < 512) {
            int slot = t >> 8, hi = t & 255;
            int nn = r + 2 * slot;
            const float* gr = g_tab + (size_t)tok * 3072 + nn * 768 + hi;
            gi_r = __ldg(gr); gi_z = __ldg(gr + 256); gi_n = __ldg(gr + 512);
            if (fbact) {
                const float* M = g_McT + nn * 768 + hi;
                for (int k = 0; k < 128; ++k) {
                    float f = sh_fb[k];
                    gi_r = fmaf(M[k * 3072], f, gi_r);
                    gi_z = fmaf(M[k * 3072 + 256], f, gi_z);
                    gi_n = fmaf(M[k * 3072 + 512], f, gi_n);
                }
            }
        }

        // ---- Region 1: warps 0-23 Whh fp16 (K-split 4, unroll 8); warps 24-31 LN+logits(s-1) ----
        if (t < 768) {
            const int ks = t / 192;
            const int grp = t - ks * 192;
            const float* hc = sh_h + 256 + ks * 64;
            unsigned long long a0 = 0ull, a1 = 0ull;
            if (ks == 0) {
                const unsigned long long* bb = (const unsigned long long*)(b_hh_c + r * 768 + grp * 4);
                a0 = bb[0]; a1 = bb[1];
            }
            const __half* wp = g_WhhT_h + (size_t)(ks * 64) * 1536 + r * 768 + grp * 4;
            #pragma unroll 8
            for (int k = 0; k < 64; ++k) {
                uint2 u = *(const uint2*)(wp + (size_t)k * 1536);
                unsigned long long xx = bcast2(hc[k]);
                ffma2(a0, pk2(__half22float2(*(const __half2*)&u.x)), xx);
                ffma2(a1, pk2(__half22float2(*(const __half2*)&u.y)), xx);
            }
            ulonglong2 st2; st2.x = a0; st2.y = a1;
            *(ulonglong2*)(scr + ks * 768 + grp * 4) = st2;
        } else if (s > 0) {
            uint32_t plp = mapa_rank(smem_u32(peerlog + p * 128), peer);
            ln_logits_own(t - 768, r, plp, gamma, beta, sh_rs, sh_on, sh_red, sh_mu, sh_rstd,
                          lnscr, ownlog);
        }
        __syncthreads();

        // ---- GRU update ----
        if (t < 512) {
            int slot = t >> 8, hi = t & 255;
            float h_old = sh_h[t];
            float ghr, ghz, ghn;
            if (slot == 0) { ghr = 0.0f; ghz = 5.0f; ghn = h_old; }
            else {
                ghr = scr[hi] + scr[768 + hi] + scr[1536 + hi] + scr[2304 + hi];
                ghz = scr[256 + hi] + scr[1024 + hi] + scr[1792 + hi] + scr[2560 + hi];
                ghn = scr[512 + hi] + scr[1280 + hi] + scr[2048 + hi] + scr[2816 + hi];
            }
            float rg = sigf(gi_r + ghr);
            float zg = sigf(gi_z + ghz);
            float ng = tanhf(fmaf(rg, ghn, gi_n));
            sh_h[t] = (1.0f - zg) * ng + zg * h_old;
        }
        __syncthreads();

        // ---- o = W_op @ h: 512 thr, fp16 global (unroll 8) ----
        if (t < 512) {
            int ks = t >> 6, pr = t & 63, slot = pr >> 5, dg = pr & 31;
            int nn = r + 2 * slot;
            const float* hrow = sh_h + slot * 256 + ks * 32;
            const __half* wp = g_WopT_h + (size_t)(ks * 32) * 512 + nn * 128 + dg * 4;
            unsigned long long a0 = 0ull, a1 = 0ull;
            #pragma unroll 8
            for (int k = 0; k < 32; ++k) {
                uint2 u = *(const uint2*)(wp + (size_t)k * 512);
                unsigned long long xx = bcast2(hrow[k]);
                ffma2(a0, pk2(__half22float2(*(const __half2*)&u.x)), xx);
                ffma2(a1, pk2(__half22float2(*(const __half2*)&u.y)), xx);
            }
            ulonglong2 st2; st2.x = a0; st2.y = a1;
            *(ulonglong2*)(scr + ks * 256 + slot * 128 + dg * 4) = st2;
        }
        __syncthreads();
        if (t < 256) {
            int slot = t >> 7, d = t & 127;
            int nn = r + 2 * slot;
            float a = 0.f;
            #pragma unroll
            for (int ks = 0; ks < 8; ++ks) a += scr[ks * 256 + t];
            sh_o[t] = a + b_op[nn * 128 + d];
        }
        __syncthreads();

        // ---- q,k,v from SMEM weights: 384 thr ----
        if (t < 384) {
            int mat = t >> 7, rr = t & 127, ks = rr >> 5, dg = rr & 31;
            const __half* WT = s_wq + mat * 16384;
            const __half* wp = WT + (size_t)(ks * 32) * 128 + dg * 4;
            const float* x0 = sh_o + ks * 32;
            const float* x1 = sh_o + 128 + ks * 32;
            unsigned long long a0 = 0, a1 = 0, b0 = 0, b1 = 0;
            #pragma unroll 4
            for (int k = 0; k < 32; ++k) {
                uint2 u = *(const uint2*)(wp + (size_t)k * 128);
                unsigned long long w0 = pk2(__half22float2(*(const __half2*)&u.x));
                unsigned long long w1 = pk2(__half22float2(*(const __half2*)&u.y));
                unsigned long long xx0 = bcast2(x0[k]), xx1 = bcast2(x1[k]);
                ffma2(a0, w0, xx0); ffma2(a1, w1, xx0);
                ffma2(b0, w0, xx1); ffma2(b1, w1, xx1);
            }
            ulonglong2 s0; s0.x = a0; s0.y = a1;
            ulonglong2 s1; s1.x = b0; s1.y = b1;
            *(ulonglong2*)(scr + ((mat * 4 + ks) * 2 + 0) * 128 + dg * 4) = s0;
            *(ulonglong2*)(scr + ((mat * 4 + ks) * 2 + 1) * 128 + dg * 4) = s1;
        }
        __syncthreads();
        {
            uint32_t kvp = mapa_rank(smem_u32(kvp_loc), peer);
            if (t < 768) {
                int mat = t >> 8, g = t & 255, slot = g >> 7, d = g & 127;
                int nn = r + 2 * slot;
                float val = 0.f;
                #pragma unroll
                for (int ks = 0; ks < 4; ++ks)
                    val += scr[((mat * 4 + ks) * 2 + slot) * 128 + d];
                if (mat == 0) sh_q[g] = val + bq[d];
                else if (mat == 1) {
                    val += bk[d];
                    kvp_loc[nn * 128 + d] = val;
                    stc_f32(kvp + (nn * 128 + d) * 4, val);
                } else {
                    val += bv[d];
                    kvp_loc[512 + nn * 128 + d] = val;
                    stc_f32(kvp + (512 + nn * 128 + d) * 4, val);
                }
            }
        }
        __syncthreads();
        CLUSTER_SYNC();

        // ---- attention scores + logit store of s-1 ----
        if (t < 256) {
            int w = t >> 5, l = t & 31, i = w >> 2, m = w & 3;
            const float* q = sh_q + i * 128;
            const float* kk = kvp_loc + m * 128;
            float sm = q[l] * kk[l] + q[32 + l] * kk[32 + l] + q[64 + l] * kk[64 + l] + q[96 + l] * kk[96 + l];
            #pragma unroll
            for (int off = 16; off; off >>= 1) sm += __shfl_down_sync(0xffffffff, sm, off);
            if (l == 0) sh_sc[i * 4 + m] = sm * inv_sqrt_d;
        } else if (s > 0 && t >= 256 && t < 306) {
            int v = r * 50 + (t - 256);
            out[(size_t)b * S_ * V_ + (size_t)(s - 1) * V_ + v] = ownlog[v] + peerlog[p * 128 + v] + br[v];
        }
        __syncthreads();

        // ---- mixed ----
        if (t < 256) {
            int slot = t >> 7, d = t & 127;
            float s0 = sh_sc[slot * 4], s1 = sh_sc[slot * 4 + 1], s2 = sh_sc[slot * 4 + 2], s3 = sh_sc[slot * 4 + 3];
            float mx = fmaxf(fmaxf(s0, s1), fmaxf(s2, s3));
            float e0 = expf(s0 - mx), e1 = expf(s1 - mx), e2 = expf(s2 - mx), e3 = expf(s3 - mx);
            float den = 1.0f / (e0 + e1 + e2 + e3);
            const float* V = kvp_loc + 512;
            sh_mx[t] = (e0 * V[d] + e1 * V[128 + d] + e2 * V[256 + d] + e3 * V[384 + d]) * den;
        }
        __syncthreads();

        // ---- f1 + GELU (SMEM weights) ----
        if (t < 256) mat128x2sh(t, s_wf1, sh_mx, scr);
        __syncthreads();
        if (t < 256) {
            int d = t & 127;
            float a = 0.f;
            #pragma unroll
            for (int ks = 0; ks < 8; ++ks) a += scr[(ks * 2 + (t >> 7)) * 128 + d];
            sh_g1[t] = geluf(a + bf1[d]);
        }
        __syncthreads();

        // ---- f2 (SMEM weights) ----
        if (t < 256) mat128x2sh(t, s_wf2, sh_g1, scr);
        __syncthreads();
        if (t < 256) {
            int d = t & 127;
            float a = 0.f;
            #pragma unroll
            for (int ks = 0; ks < 8; ++ks) a += scr[(ks * 2 + (t >> 7)) * 128 + d];
            sh_pc[t] = a + bf2[d];
        }
        __syncthreads();

        // ---- wo (global fp16) ----
        if (t < 256) {
            int ks = t >> 5, dg = t & 31;
            const __half* wp = g_WwoT_h + (size_t)(ks * 16) * 128 + dg * 4;
            const float* x0 = sh_pc + ks * 16;
            const float* x1 = sh_pc + 128 + ks * 16;
            unsigned long long a0 = 0, a1 = 0, b0 = 0, b1 = 0;
            #pragma unroll
            for (int k = 0; k < 16; ++k) {
                uint2 u = *(const uint2*)(wp + (size_t)k * 128);
                unsigned long long w0 = pk2(__half22float2(*(const __half2*)&u.x));
                unsigned long long w1 = pk2(__half22float2(*(const __half2*)&u.y));
                unsigned long long xx0 = bcast2(x0[k]), xx1 = bcast2(x1[k]);
                ffma2(a0, w0, xx0); ffma2(a1, w1, xx0);
                ffma2(b0, w0, xx1); ffma2(b1, w1, xx1);
            }
            ulonglong2 s0; s0.x = a0; s0.y = a1;
            ulonglong2 s1; s1.x = b0; s1.y = b1;
            *(ulonglong2*)(scr + (ks * 2 + 0) * 128 + dg * 4) = s0;
            *(ulonglong2*)(scr + (ks * 2 + 1) * 128 + dg * 4) = s1;
        }
        __syncthreads();
        if (t < 256) {
            int d = t & 127;
            float a = 0.f;
            #pragma unroll
            for (int ks = 0; ks < 8; ++ks) a += scr[(ks * 2 + (t >> 7)) * 128 + d];
            sh_rs[t] = sh_o[t] + a + bwo[d];
        }
        if (fbact && t < 128) {
            float fbp = 0.25f * (sh_pc[t] + sh_pc[128 + t]);
            sh_fbown[t] = fbp;
            uint32_t fxp = mapa_rank(smem_u32(fbx + p * 128), peer);
            stc_f32(fxp + t * 4, fbp);
        }
        __syncthreads();
        if (fbact) {
            CLUSTER_SYNC();
            if (t < 128) sh_fb[t] = sh_fbown[t] + fbx[p * 128 + t];
            __syncthreads();
        }
    }

    // ---- final step's LN + logits + fb exchange ----
    if (t >= 768) {
        uint32_t plp = mapa_rank(smem_u32(peerlog), peer);
        ln_logits_own(t - 768, r, plp, gamma, beta, sh_rs, sh_on, sh_red, sh_mu, sh_rstd,
                      lnscr, ownlog);
    }
    if (!fbact && t < 128) {
        float fbp = 0.25f * (sh_pc[t] + sh_pc[128 + t]);
        sh_fbown[t] = fbp;
        uint32_t fxp = mapa_rank(smem_u32(fbx), peer);
        stc_f32(fxp + t * 4, fbp);
    }
    __syncthreads();
    CLUSTER_SYNC();

    if (t < 50) {
        int v = r * 50 + t;
        out[(size_t)b * S_ * V_ + (size_t)(S_ - 1) * V_ + v] = ownlog[v] + peerlog[v] + br[v];
    }
    if (write_states) {
        size_t OFF1 = (size_t)B_ * S_ * V_;
        if (t < 512) {
            int slot = t >> 8, hi = t & 255;
            int nn = r + 2 * slot;
            out[OFF1 + (size_t)nn * B_ * H_ + (size_t)b * H_ + hi] = sh_h[t];
        }
        if (r == 0 && t < 128) {
            float fbv = fbact ? sh_fb[t] : (sh_fbown[t] + fbx[t]);
            out[OFF1 + (size_t)N_ * B_ * H_ + (size_t)b * D_ + t] = fbv;
        }
    }
}

extern "C" void kernel_launch(void* const* d_in, const int* in_sizes, int n_in,
                              void* d_out, int out_size)
{
    const int*   x      = (const int*)  d_in[0];
    const float* emb    = (const float*)d_in[1];
    const float* W_ih   = (const float*)d_in[2];
    const float* b_ih   = (const float*)d_in[3];
    const float* W_hh_c = (const float*)d_in[4];
    const float* b_hh_c = (const float*)d_in[5];
    const float* W_op   = (const float*)d_in[6];
    const float* b_op   = (const float*)d_in[7];
    const float* Wq     = (const float*)d_in[8];
    const float* bq     = (const float*)d_in[9];
    const float* Wk     = (const float*)d_in[10];
    const float* bk     = (const float*)d_in[11];
    const float* Wv     = (const float*)d_in[12];
    const float* bv     = (const float*)d_in[13];
    const float* Wf1    = (const float*)d_in[14];
    const float* bf1    = (const float*)d_in[15];
    const float* Wf2    = (const float*)d_in[16];
    const float* bf2    = (const float*)d_in[17];
    const float* Wwo    = (const float*)d_in[18];
    const float* bwo    = (const float*)d_in[19];
    const float* gamma  = (const float*)d_in[20];
    const float* beta   = (const float*)d_in[21];
    const float* Wr     = (const float*)d_in[22];
    const float* br     = (const float*)d_in[23];
    const float* Wfb    = (const float*)d_in[24];
    const float* bfb    = (const float*)d_in[25];
    float* out = (float*)d_out;

    cudaFuncSetAttribute(inn_kernel, cudaFuncAttributeMaxDynamicSharedMemorySize, SMEM_BYTES);

    prep_all<<<512, 256>>>(W_ih, b_ih, W_hh_c, W_op, Wq, Wk, Wv, Wf1, Wf2, Wwo, Wr, Wfb, bfb, emb);

    long long FULL = (long long)B_ * S_ * V_ + (long long)N_ * B_ * H_ + (long long)B_ * D_;
    int write_states = ((long long)out_size >= FULL) ? 1 : 0;

    inn_kernel<<<2 * B_, 1024, SMEM_BYTES>>>(x, b_hh_c, b_op, bq, bk, bv, bf1, bf2, bwo,
                                             gamma, beta, br, out, write_states);
}

// round 16
// speedup vs baseline: 1.1283x; 1.1283x over previous
#include <cuda_runtime.h>
#include <cuda_fp16.h>
#include <math.h>
#include <stdint.h>

#define S_ 2048
#define V_ 100
#define B_ 64
#define H_ 256
#define N_ 4
#define D_ 128

__device__ __align__(16) __half g_WhhT_h[256 * 1536];
__device__ __align__(16) __half g_WopT_h[256 * 512];
__device__ __align__(16) __half g_WqT_h [16384], g_WkT_h [16384], g_WvT_h [16384];
__device__ __align__(16) __half g_Wf1T_h[16384], g_Wf2T_h[16384], g_WwoT_h[16384];
__device__ __align__(16) __half g_WrT_h [512 * 100];     // coalesced [k*100+v] (R14 layout)
__device__ __align__(16) float g_tab [100 * 3072];
__device__ __align__(16) float g_McT [128 * 3072];
__device__ int g_fb_active;

// smem layout (bytes): 6 fp16 mats (q,k,v,f1,f2,wo) then float region
#define SM_F       196608
#define NFLOATS    8604
#define SMEM_BYTES (196608 + NFLOATS * 4)    // 231024 <= 232448 limit

__device__ __forceinline__ void ffma2(unsigned long long& d, unsigned long long a, unsigned long long b) {
    asm("fma.rn.f32x2 %0, %1, %2, %3;" : "=l"(d) : "l"(a), "l"(b), "l"(d));
}
__device__ __forceinline__ unsigned long long bcast2(float x) {
    unsigned long long r; asm("mov.b64 %0, {%1, %1};" : "=l"(r) : "f"(x)); return r;
}
__device__ __forceinline__ unsigned long long pk2(float2 f) {
    unsigned long long r; asm("mov.b64 %0, {%1, %2};" : "=l"(r) : "f"(f.x), "f"(f.y)); return r;
}
__device__ __forceinline__ float sigf(float x) { return 1.0f / (1.0f + expf(-x)); }
__device__ __forceinline__ float geluf(float x) { return 0.5f * x * (1.0f + erff(x * 0.7071067811865475f)); }

__device__ __forceinline__ uint32_t smem_u32(const void* p) { return (uint32_t)__cvta_generic_to_shared(p); }
__device__ __forceinline__ uint32_t mapa_rank(uint32_t a, uint32_t rk) {
    uint32_t r; asm("mapa.shared::cluster.u32 %0, %1, %2;" : "=r"(r) : "r"(a), "r"(rk)); return r;
}
__device__ __forceinline__ void stc_f32(uint32_t a, float v) {
    asm volatile("st.shared::cluster.f32 [%0], %1;" :: "r"(a), "f"(v) : "memory");
}
#define CLUSTER_SYNC() do { \
    asm volatile("barrier.cluster.arrive.aligned;" ::: "memory"); \
    asm volatile("barrier.cluster.wait.aligned;" ::: "memory"); } while (0)

// ---------------- prep (single kernel) ----------------
__global__ void prep_all(const float* __restrict__ W_ih, const float* __restrict__ b_ih,
                         const float* __restrict__ W_hh_c, const float* __restrict__ W_op,
                         const float* __restrict__ Wq, const float* __restrict__ Wk,
                         const float* __restrict__ Wv, const float* __restrict__ Wf1,
                         const float* __restrict__ Wf2, const float* __restrict__ Wwo,
                         const float* __restrict__ Wr, const float* __restrict__ Wfb,
                         const float* __restrict__ bfb, const float* __restrict__ emb)
{
    int i = blockIdx.x * blockDim.x + threadIdx.x, st = gridDim.x * blockDim.x;
    for (int p = i; p < 256 * 1536; p += st) { int k = p / 1536, o = p - k * 1536; g_WhhT_h[p] = __float2half_rn(W_hh_c[o * 256 + k]); }
    for (int p = i; p < 256 * 512;  p += st) { int k = p >> 9,  o = p & 511;       g_WopT_h[p] = __float2half_rn(W_op[o * 256 + k]); }
    for (int p = i; p < 16384; p += st) {
        int k = p >> 7, d = p & 127;
        g_WqT_h [p] = __float2half_rn(Wq [d * 128 + k]);
        g_WkT_h [p] = __float2half_rn(Wk [d * 128 + k]);
        g_WvT_h [p] = __float2half_rn(Wv [d * 128 + k]);
        g_Wf1T_h[p] = __float2half_rn(Wf1[d * 128 + k]);
        g_Wf2T_h[p] = __float2half_rn(Wf2[d * 128 + k]);
        g_WwoT_h[p] = __float2half_rn(Wwo[d * 128 + k]);
    }
    for (int p = i; p < 512 * 100; p += st) { int k = p / 100, v = p - k * 100; g_WrT_h[p] = __float2half_rn(Wr[v * 512 + k]); }
    for (int p = i; p < 100 * 3072; p += st) {
        int v = p / 3072, o = p - v * 3072;
        const float* wr = W_ih + (size_t)o * 128;
        const float* ev = emb + (size_t)v * 128;
        float acc = b_ih[o];
        #pragma unroll 8
        for (int k = 0; k < 128; ++k) acc = fmaf(wr[k], ev[k] + bfb[k], acc);
        g_tab[p] = acc;
    }
    for (int p = i; p < 128 * 3072; p += st) {
        int kk = p / 3072, o = p - kk * 3072;
        const float* wr = W_ih + (size_t)o * 128;
        const float* fr = Wfb + (size_t)kk * 128;
        float acc = 0.0f;
        #pragma unroll 8
        for (int j = 0; j < 128; ++j) acc = fmaf(wr[j], fr[j], acc);
        g_McT[p] = acc;
    }
    if (blockIdx.x == 0) {
        __shared__ int s_nz;
        if (threadIdx.x == 0) s_nz = 0;
        __syncthreads();
        int nz = 0;
        for (int p = threadIdx.x; p < 16384; p += blockDim.x) if (Wfb[p] != 0.0f) nz = 1;
        for (int p = threadIdx.x; p < 128; p += blockDim.x) if (bfb[p] != 0.0f) nz = 1;
        if (nz) atomicOr(&s_nz, 1);
        __syncthreads();
        if (threadIdx.x == 0) g_fb_active = s_nz;
    }
}

// ---- LayerNorm + logits partial for own 2 neurons; 256 threads, named barrier 1 ----
__device__ __forceinline__ void ln_logits_own(
    int u, int r, uint32_t peerlog_paddr,
    const float* __restrict__ gamma, const float* __restrict__ beta,
    const float* sh_rs, float* sh_on, float* sh_red, float* sh_mu, float* sh_rstd,
    float* lnscr, float* ownlog)
{
    int row = u >> 7, d = u & 127, w8 = u >> 5, l = u & 31;
    float v = sh_rs[u];
    float sum = v, sq = v * v;
    #pragma unroll
    for (int off = 16; off; off >>= 1) {
        sum += __shfl_down_sync(0xffffffff, sum, off);
        sq  += __shfl_down_sync(0xffffffff, sq,  off);
    }
    if (l == 0) { sh_red[w8 * 2] = sum; sh_red[w8 * 2 + 1] = sq; }
    asm volatile("bar.sync 1, 256;" ::: "memory");
    if (u < 2) {
        float s = 0.f, q = 0.f;
        #pragma unroll
        for (int j = 0; j < 4; ++j) { s += sh_red[(u * 4 + j) * 2]; q += sh_red[(u * 4 + j) * 2 + 1]; }
        float mu = s * (1.0f / 128.0f);
        sh_mu[u] = mu;
        sh_rstd[u] = rsqrtf(q * (1.0f / 128.0f) - mu * mu + 1e-5f);
    }
    asm volatile("bar.sync 1, 256;" ::: "memory");
    sh_on[u] = (sh_rs[u] - sh_mu[row]) * sh_rstd[row] * gamma[d] + beta[d];
    asm volatile("bar.sync 1, 256;" ::: "memory");
    {
        float a = 0.0f;
        if (d < V_) {
            int nn = r + 2 * row;
            const __half* W = g_WrT_h + (size_t)(nn * 128) * 100 + d;
            const float* on = sh_on + row * 128;
            #pragma unroll 8
            for (int k = 0; k < 128; ++k) a = fmaf(__half2float(W[k * 100]), on[k], a);
        }
        lnscr[u] = a;
    }
    asm volatile("bar.sync 1, 256;" ::: "memory");
    if (u < 128) {
        float tot = lnscr[u] + lnscr[128 + u];
        ownlog[u] = tot;
        stc_f32(peerlog_paddr + u * 4, tot);
    }
}

// ---- fp16 128x128 matvec on own 2 rows from SMEM weights: 256 threads ----
__device__ __forceinline__ void mat128x2sh(int t, const __half* WT,
                                           const float* src, float* scr)
{
    int ks = t >> 5, dg = t & 31;
    const __half* wp = WT + (size_t)(ks * 16) * 128 + dg * 4;
    const float* x0 = src + ks * 16;
    const float* x1 = src + 128 + ks * 16;
    unsigned long long a0 = 0, a1 = 0, b0 = 0, b1 = 0;
    #pragma unroll
    for (int k = 0; k < 16; ++k) {
        uint2 u = *(const uint2*)(wp + (size_t)k * 128);
        unsigned long long w0 = pk2(__half22float2(*(const __half2*)&u.x));
        unsigned long long w1 = pk2(__half22float2(*(const __half2*)&u.y));
        unsigned long long xx0 = bcast2(x0[k]), xx1 = bcast2(x1[k]);
        ffma2(a0, w0, xx0); ffma2(a1, w1, xx0);
        ffma2(b0, w0, xx1); ffma2(b1, w1, xx1);
    }
    ulonglong2 s0; s0.x = a0; s0.y = a1;
    ulonglong2 s1; s1.x = b0; s1.y = b1;
    *(ulonglong2*)(scr + (ks * 2 + 0) * 128 + dg * 4) = s0;
    *(ulonglong2*)(scr + (ks * 2 + 1) * 128 + dg * 4) = s1;
}

__global__ void __launch_bounds__(1024, 1) __cluster_dims__(2, 1, 1)
inn_kernel(const int* __restrict__ x,
           const float* __restrict__ b_hh_c, const float* __restrict__ b_op,
           const float* __restrict__ bq, const float* __restrict__ bk, const float* __restrict__ bv,
           const float* __restrict__ bf1, const float* __restrict__ bf2, const float* __restrict__ bwo,
           const float* __restrict__ gamma, const float* __restrict__ beta,
           const float* __restrict__ br,
           float* __restrict__ out, int write_states)
{
    extern __shared__ __align__(16) char smraw[];
    __half* s_wq  = (__half*)(smraw);
    __half* s_wf1 = s_wq + 3 * 16384;
    __half* s_wf2 = s_wf1 + 16384;
    __half* s_wwo = s_wf2 + 16384;
    float* fb_    = (float*)(smraw + SM_F);
    float* sh_h     = fb_;            // 512
    float* scr      = sh_h + 512;     // 3072
    float* lnscr    = scr + 3072;     // 256
    float* kv_all   = lnscr + 256;    // 2048 (2 x 1024)
    float* sh_o     = kv_all + 2048;  // 256
    float* sh_q     = sh_o + 256;     // 256
    float* sh_mx    = sh_q + 256;     // 256
    float* sh_g1    = sh_mx + 256;    // 256
    float* sh_pc    = sh_g1 + 256;    // 256
    float* sh_rs    = sh_pc + 256;    // 256
    float* sh_on    = sh_rs + 256;    // 256
    float* peerlog  = sh_on + 256;    // 256 (2 x 128)
    float* ownlog   = peerlog + 256;  // 128
    float* fbx      = ownlog + 128;   // 256 (2 x 128)
    float* sh_fbown = fbx + 256;      // 128
    float* sh_fb    = sh_fbown + 128; // 128
    float* sh_sc    = sh_fb + 128;    // 8
    float* sh_red   = sh_sc + 8;      // 16
    float* sh_mu    = sh_red + 16;    // 2
    float* sh_rstd  = sh_mu + 2;      // 2

    const int b = blockIdx.x >> 1;
    const int r = blockIdx.x & 1;
    const uint32_t peer = (uint32_t)(r ^ 1);
    const int t = threadIdx.x;

    #pragma unroll
    for (int m = 0; m < 6; ++m) {
        const __half* src = (m == 0) ? g_WqT_h : (m == 1) ? g_WkT_h : (m == 2) ? g_WvT_h
                          : (m == 3) ? g_Wf1T_h : (m == 4) ? g_Wf2T_h : g_WwoT_h;
        uint4* dst = (uint4*)(s_wq + m * 16384);
        for (int i = t; i < 2048; i += 1024) dst[i] = ((const uint4*)src)[i];
    }
    if (t < 512) sh_h[t] = 0.0f;
    if (t < 128) sh_fb[t] = 0.0f;
    const int fbact = g_fb_active;
    __syncthreads();

    const float inv_sqrt_d = 0.08838834764831845f;

    for (int s = 0; s < S_; ++s) {
        const int p = s & 1;
        float* kvp_loc = kv_all + p * 1024;
        const int tok = __ldg(x + b * S_ + s);

        float gi_r = 0.f, gi_z = 0.f, gi_n = 0.f;
        if (t < 512) {
            int slot = t >> 8, hi = t & 255;
            int nn = r + 2 * slot;
            const float* gr = g_tab + (size_t)tok * 3072 + nn * 768 + hi;
            gi_r = __ldg(gr); gi_z = __ldg(gr + 256); gi_n = __ldg(gr + 512);
            if (fbact) {
                const float* M = g_McT + nn * 768 + hi;
                for (int k = 0; k < 128; ++k) {
                    float f = sh_fb[k];
                    gi_r = fmaf(M[k * 3072], f, gi_r);
                    gi_z = fmaf(M[k * 3072 + 256], f, gi_z);
                    gi_n = fmaf(M[k * 3072 + 512], f, gi_n);
                }
            }
        }

        // ---- Region 1: warps 0-23 Whh fp16 (K-split 4, unroll 8); warps 24-31 LN+logits(s-1) ----
        if (t < 768) {
            const int ks = t / 192;
            const int grp = t - ks * 192;
            const float* hc = sh_h + 256 + ks * 64;
            unsigned long long a0 = 0ull, a1 = 0ull;
            if (ks == 0) {
                const unsigned long long* bb = (const unsigned long long*)(b_hh_c + r * 768 + grp * 4);
                a0 = bb[0]; a1 = bb[1];
            }
            const __half* wp = g_WhhT_h + (size_t)(ks * 64) * 1536 + r * 768 + grp * 4;
            #pragma unroll 8
            for (int k = 0; k < 64; ++k) {
                uint2 u = *(const uint2*)(wp + (size_t)k * 1536);
                unsigned long long xx = bcast2(hc[k]);
                ffma2(a0, pk2(__half22float2(*(const __half2*)&u.x)), xx);
                ffma2(a1, pk2(__half22float2(*(const __half2*)&u.y)), xx);
            }
            ulonglong2 st2; st2.x = a0; st2.y = a1;
            *(ulonglong2*)(scr + ks * 768 + grp * 4) = st2;
        } else if (s > 0) {
            uint32_t plp = mapa_rank(smem_u32(peerlog + p * 128), peer);
            ln_logits_own(t - 768, r, plp, gamma, beta, sh_rs, sh_on, sh_red, sh_mu, sh_rstd,
                          lnscr, ownlog);
        }
        __syncthreads();

        // ---- GRU update ----
        if (t < 512) {
            int slot = t >> 8, hi = t & 255;
            float h_old = sh_h[t];
            float ghr, ghz, ghn;
            if (slot == 0) { ghr = 0.0f; ghz = 5.0f; ghn = h_old; }
            else {
                ghr = scr[hi] + scr[768 + hi] + scr[1536 + hi] + scr[2304 + hi];
                ghz = scr[256 + hi] + scr[1024 + hi] + scr[1792 + hi] + scr[2560 + hi];
                ghn = scr[512 + hi] + scr[1280 + hi] + scr[2048 + hi] + scr[2816 + hi];
            }
            float rg = sigf(gi_r + ghr);
            float zg = sigf(gi_z + ghz);
            float ng = tanhf(fmaf(rg, ghn, gi_n));
            sh_h[t] = (1.0f - zg) * ng + zg * h_old;
        }
        __syncthreads();

        // ---- o = W_op @ h: 512 thr, fp16 global (unroll 8) ----
        if (t < 512) {
            int ks = t >> 6, pr = t & 63, slot = pr >> 5, dg = pr & 31;
            int nn = r + 2 * slot;
            const float* hrow = sh_h + slot * 256 + ks * 32;
            const __half* wp = g_WopT_h + (size_t)(ks * 32) * 512 + nn * 128 + dg * 4;
            unsigned long long a0 = 0ull, a1 = 0ull;
            #pragma unroll 8
            for (int k = 0; k < 32; ++k) {
                uint2 u = *(const uint2*)(wp + (size_t)k * 512);
                unsigned long long xx = bcast2(hrow[k]);
                ffma2(a0, pk2(__half22float2(*(const __half2*)&u.x)), xx);
                ffma2(a1, pk2(__half22float2(*(const __half2*)&u.y)), xx);
            }
            ulonglong2 st2; st2.x = a0; st2.y = a1;
            *(ulonglong2*)(scr + ks * 256 + slot * 128 + dg * 4) = st2;
        }
        __syncthreads();
        if (t < 256) {
            int slot = t >> 7, d = t & 127;
            int nn = r + 2 * slot;
            float a = 0.f;
            #pragma unroll
            for (int ks = 0; ks < 8; ++ks) a += scr[ks * 256 + t];
            sh_o[t] = a + b_op[nn * 128 + d];
        }
        __syncthreads();

        // ---- q,k,v from SMEM weights: 384 thr ----
        if (t < 384) {
            int mat = t >> 7, rr = t & 127, ks = rr >> 5, dg = rr & 31;
            const __half* WT = s_wq + mat * 16384;
            const __half* wp = WT + (size_t)(ks * 32) * 128 + dg * 4;
            const float* x0 = sh_o + ks * 32;
            const float* x1 = sh_o + 128 + ks * 32;
            unsigned long long a0 = 0, a1 = 0, b0 = 0, b1 = 0;
            #pragma unroll 4
            for (int k = 0; k < 32; ++k) {
                uint2 u = *(const uint2*)(wp + (size_t)k * 128);
                unsigned long long w0 = pk2(__half22float2(*(const __half2*)&u.x));
                unsigned long long w1 = pk2(__half22float2(*(const __half2*)&u.y));
                unsigned long long xx0 = bcast2(x0[k]), xx1 = bcast2(x1[k]);
                ffma2(a0, w0, xx0); ffma2(a1, w1, xx0);
                ffma2(b0, w0, xx1); ffma2(b1, w1, xx1);
            }
            ulonglong2 s0; s0.x = a0; s0.y = a1;
            ulonglong2 s1; s1.x = b0; s1.y = b1;
            *(ulonglong2*)(scr + ((mat * 4 + ks) * 2 + 0) * 128 + dg * 4) = s0;
            *(ulonglong2*)(scr + ((mat * 4 + ks) * 2 + 1) * 128 + dg * 4) = s1;
        }
        __syncthreads();
        {
            uint32_t kvp = mapa_rank(smem_u32(kvp_loc), peer);
            if (t < 768) {
                int mat = t >> 8, g = t & 255, slot = g >> 7, d = g & 127;
                int nn = r + 2 * slot;
                float val = 0.f;
                #pragma unroll
                for (int ks = 0; ks < 4; ++ks)
                    val += scr[((mat * 4 + ks) * 2 + slot) * 128 + d];
                if (mat == 0) sh_q[g] = val + bq[d];
                else if (mat == 1) {
                    val += bk[d];
                    kvp_loc[nn * 128 + d] = val;
                    stc_f32(kvp + (nn * 128 + d) * 4, val);
                } else {
                    val += bv[d];
                    kvp_loc[512 + nn * 128 + d] = val;
                    stc_f32(kvp + (512 + nn * 128 + d) * 4, val);
                }
            }
        }
        __syncthreads();
        CLUSTER_SYNC();

        // ---- attention scores + logit store of s-1 ----
        if (t < 256) {
            int w = t >> 5, l = t & 31, i = w >> 2, m = w & 3;
            const float* q = sh_q + i * 128;
            const float* kk = kvp_loc + m * 128;
            float sm = q[l] * kk[l] + q[32 + l] * kk[32 + l] + q[64 + l] * kk[64 + l] + q[96 + l] * kk[96 + l];
            #pragma unroll
            for (int off = 16; off; off >>= 1) sm += __shfl_down_sync(0xffffffff, sm, off);
            if (l == 0) sh_sc[i * 4 + m] = sm * inv_sqrt_d;
        } else if (s > 0 && t >= 256 && t < 306) {
            int v = r * 50 + (t - 256);
            out[(size_t)b * S_ * V_ + (size_t)(s - 1) * V_ + v] = ownlog[v] + peerlog[p * 128 + v] + br[v];
        }
        __syncthreads();

        // ---- mixed ----
        if (t < 256) {
            int slot = t >> 7, d = t & 127;
            float s0 = sh_sc[slot * 4], s1 = sh_sc[slot * 4 + 1], s2 = sh_sc[slot * 4 + 2], s3 = sh_sc[slot * 4 + 3];
            float mx = fmaxf(fmaxf(s0, s1), fmaxf(s2, s3));
            float e0 = expf(s0 - mx), e1 = expf(s1 - mx), e2 = expf(s2 - mx), e3 = expf(s3 - mx);
            float den = 1.0f / (e0 + e1 + e2 + e3);
            const float* V = kvp_loc + 512;
            sh_mx[t] = (e0 * V[d] + e1 * V[128 + d] + e2 * V[256 + d] + e3 * V[384 + d]) * den;
        }
        __syncthreads();

        // ---- f1 + GELU (SMEM weights) ----
        if (t < 256) mat128x2sh(t, s_wf1, sh_mx, scr);
        __syncthreads();
        if (t < 256) {
            int d = t & 127;
            float a = 0.f;
            #pragma unroll
            for (int ks = 0; ks < 8; ++ks) a += scr[(ks * 2 + (t >> 7)) * 128 + d];
            sh_g1[t] = geluf(a + bf1[d]);
        }
        __syncthreads();

        // ---- f2 (SMEM weights) ----
        if (t < 256) mat128x2sh(t, s_wf2, sh_g1, scr);
        __syncthreads();
        if (t < 256) {
            int d = t & 127;
            float a = 0.f;
            #pragma unroll
            for (int ks = 0; ks < 8; ++ks) a += scr[(ks * 2 + (t >> 7)) * 128 + d];
            sh_pc[t] = a + bf2[d];
        }
        __syncthreads();

        // ---- wo (SMEM weights) ----
        if (t < 256) mat128x2sh(t, s_wwo, sh_pc, scr);
        __syncthreads();
        if (t < 256) {
            int d = t & 127;
            float a = 0.f;
            #pragma unroll
            for (int ks = 0; ks < 8; ++ks) a += scr[(ks * 2 + (t >> 7)) * 128 + d];
            sh_rs[t] = sh_o[t] + a + bwo[d];
        }
        if (fbact && t < 128) {
            float fbp = 0.25f * (sh_pc[t] + sh_pc[128 + t]);
            sh_fbown[t] = fbp;
            uint32_t fxp = mapa_rank(smem_u32(fbx + p * 128), peer);
            stc_f32(fxp + t * 4, fbp);
        }
        __syncthreads();
        if (fbact) {
            CLUSTER_SYNC();
            if (t < 128) sh_fb[t] = sh_fbown[t] + fbx[p * 128 + t];
            __syncthreads();
        }
    }

    // ---- final step's LN + logits + fb exchange ----
    if (t >= 768) {
        uint32_t plp = mapa_rank(smem_u32(peerlog), peer);
        ln_logits_own(t - 768, r, plp, gamma, beta, sh_rs, sh_on, sh_red, sh_mu, sh_rstd,
                      lnscr, ownlog);
    }
    if (!fbact && t < 128) {
        float fbp = 0.25f * (sh_pc[t] + sh_pc[128 + t]);
        sh_fbown[t] = fbp;
        uint32_t fxp = mapa_rank(smem_u32(fbx), peer);
        stc_f32(fxp + t * 4, fbp);
    }
    __syncthreads();
    CLUSTER_SYNC();

    if (t < 50) {
        int v = r * 50 + t;
        out[(size_t)b * S_ * V_ + (size_t)(S_ - 1) * V_ + v] = ownlog[v] + peerlog[v] + br[v];
    }
    if (write_states) {
        size_t OFF1 = (size_t)B_ * S_ * V_;
        if (t < 512) {
            int slot = t >> 8, hi = t & 255;
            int nn = r + 2 * slot;
            out[OFF1 + (size_t)nn * B_ * H_ + (size_t)b * H_ + hi] = sh_h[t];
        }
        if (r == 0 && t < 128) {
            float fbv = fbact ? sh_fb[t] : (sh_fbown[t] + fbx[t]);
            out[OFF1 + (size_t)N_ * B_ * H_ + (size_t)b * D_ + t] = fbv;
        }
    }
}

extern "C" void kernel_launch(void* const* d_in, const int* in_sizes, int n_in,
                              void* d_out, int out_size)
{
    const int*   x      = (const int*)  d_in[0];
    const float* emb    = (const float*)d_in[1];
    const float* W_ih   = (const float*)d_in[2];
    const float* b_ih   = (const float*)d_in[3];
    const float* W_hh_c = (const float*)d_in[4];
    const float* b_hh_c = (const float*)d_in[5];
    const float* W_op   = (const float*)d_in[6];
    const float* b_op   = (const float*)d_in[7];
    const float* Wq     = (const float*)d_in[8];
    const float* bq     = (const float*)d_in[9];
    const float* Wk     = (const float*)d_in[10];
    const float* bk     = (const float*)d_in[11];
    const float* Wv     = (const float*)d_in[12];
    const float* bv     = (const float*)d_in[13];
    const float* Wf1    = (const float*)d_in[14];
    const float* bf1    = (const float*)d_in[15];
    const float* Wf2    = (const float*)d_in[16];
    const float* bf2    = (const float*)d_in[17];
    const float* Wwo    = (const float*)d_in[18];
    const float* bwo    = (const float*)d_in[19];
    const float* gamma  = (const float*)d_in[20];
    const float* beta   = (const float*)d_in[21];
    const float* Wr     = (const float*)d_in[22];
    const float* br     = (const float*)d_in[23];
    const float* Wfb    = (const float*)d_in[24];
    const float* bfb    = (const float*)d_in[25];
    float* out = (float*)d_out;

    cudaFuncSetAttribute(inn_kernel, cudaFuncAttributeMaxDynamicSharedMemorySize, SMEM_BYTES);

    prep_all<<<512, 256>>>(W_ih, b_ih, W_hh_c, W_op, Wq, Wk, Wv, Wf1, Wf2, Wwo, Wr, Wfb, bfb, emb);

    long long FULL = (long long)B_ * S_ * V_ + (long long)N_ * B_ * H_ + (long long)B_ * D_;
    int write_states = ((long long)out_size >= FULL) ? 1 : 0;

    inn_kernel<<<2 * B_, 1024, SMEM_BYTES>>>(x, b_hh_c, b_op, bq, bk, bv, bf1, bf2, bwo,
                                             gamma, beta, br, out, write_states);
}